// round 16
// baseline (speedup 1.0000x reference)
#include <cuda_runtime.h>
#include <math.h>

typedef unsigned long long ull;

#define GN 40000
#define PN 5
#define UVE 65536
#define TM 64

__device__ __forceinline__ ull fma2(ull a, ull b, ull c) {
    ull d; asm("fma.rn.f32x2 %0, %1, %2, %3;" : "=l"(d) : "l"(a), "l"(b), "l"(c)); return d;
}
__device__ __forceinline__ ull pack2(float lo, float hi) {
    ull d; asm("mov.b64 %0, {%1, %2};" : "=l"(d) : "f"(lo), "f"(hi)); return d;
}
__device__ __forceinline__ void unpack2(ull v, float& lo, float& hi) {
    asm("mov.b64 {%0, %1}, %2;" : "=f"(lo), "=f"(hi) : "l"(v));
}
__device__ __forceinline__ unsigned smem_u32(const void* p) {
    unsigned a;
    asm("{ .reg .u64 t; cvta.to.shared.u64 t, %1; cvt.u32.u64 %0, t; }" : "=r"(a) : "l"(p));
    return a;
}
__device__ __forceinline__ void cpa16(unsigned dst, const float* src) {
    asm volatile("cp.async.cg.shared.global [%0], [%1], 16;" :: "r"(dst), "l"(src));
}
__device__ __forceinline__ void cpcommit() { asm volatile("cp.async.commit_group;"); }
__device__ __forceinline__ void cpwait1() { asm volatile("cp.async.wait_group 1;"); }
__device__ __forceinline__ void cpwait0() { asm volatile("cp.async.wait_group 0;"); }

// ---------- scratch ----------
__device__ int    g_counts[8];
__device__ int    g_offsets[8];
__device__ int    g_cursor[8];
__device__ int    g_tile_part[640];
__device__ int    g_tile_start[640];
__device__ int    g_ntiles;
__device__ int    g_order[GN];
__device__ float  g_uvmap[32 * UVE];
__device__ float  g_bufA[64 * UVE];
__device__ float  g_bufB[64 * UVE];
__device__ float  g_psumA[64 * 512];
__device__ float  g_psumsqA[64 * 512];
__device__ float  g_psumB[64 * 512];
__device__ float  g_psumsqB[64 * 512];
__device__ float  g_wtf[129024];  // k-major: in[cin32][k9][co64]@0 ; hid[l][cin64][k9][co64]@18432
__device__ float2 g_wt[1728];     // convout dup: [cin64][co3][9]

// ---------- bucketing ----------
__global__ void count_k(const int* __restrict__ part, int* counts) {
    int g = blockIdx.x * blockDim.x + threadIdx.x;
    if (g < GN) atomicAdd(&counts[part[g]], 1);
}
__global__ void scan_k(const int* __restrict__ counts, int* offsets, int* cursor,
                       int* tile_part, int* tile_start, int* ntiles) {
    if (threadIdx.x == 0) {
        int s = 0, nt = 0;
        for (int p = 0; p < PN; p++) {
            offsets[p] = s; cursor[p] = s;
            for (int st = s; st < s + counts[p]; st += TM) {
                tile_part[nt] = p; tile_start[nt] = st; nt++;
            }
            s += counts[p];
        }
        offsets[PN] = s;
        *ntiles = nt;
    }
}
__global__ void scatter_k(const int* __restrict__ part, int* cursor, int* __restrict__ order) {
    int g = blockIdx.x * blockDim.x + threadIdx.x;
    if (g < GN) { int pos = atomicAdd(&cursor[part[g]], 1); order[pos] = g; }
}

// ---------- conv weight transpose ----------
__global__ void wprep_k(const float* __restrict__ win, const float* __restrict__ whid,
                        const float* __restrict__ wout, float* __restrict__ wtf,
                        float2* __restrict__ wt) {
    int i = blockIdx.x * 256 + threadIdx.x;
    if (i < 18432) {
        int k = i % 9; int t = i / 9; int co = t % 64, cin = t / 64;
        wtf[cin * 576 + k * 64 + co] = win[(co * 32 + cin) * 9 + k];
    }
    if (i < 110592) {
        int k = i % 9; int t = i / 9; int co = t % 64;
        int t2 = t / 64; int cin = t2 % 64, l = t2 / 64;
        wtf[18432 + l * 36864 + cin * 576 + k * 64 + co] = whid[((l * 64 + co) * 64 + cin) * 9 + k];
    }
    if (i < 1728) {
        int k = i % 9; int t = i / 9; int co = t % 3, cin = t / 3;
        float v = wout[(co * 64 + cin) * 9 + k];
        wt[i] = make_float2(v, v);
    }
}

// ---------- fused MLP: col-pack compute + cp.async per-warp weight staging (R14) ----------
__device__ __forceinline__ void layer2(
    const float* A, int K, int NC,
    const float* __restrict__ W, const float* __restrict__ bias,
    float* Out, float* Bs, unsigned bs_u32, int tid)
{
    const int w = tid >> 5, lane = tid & 31;
    const int r0 = (lane & 15) << 2;
    const int c0 = (w << 4) + ((lane >> 4) << 3);
    const int wc0 = w << 4;

    ull acc[4][4];
#pragma unroll
    for (int r = 0; r < 4; r++)
#pragma unroll
        for (int cp = 0; cp < 4; cp++) acc[r][cp] = 0ull;

    const unsigned bw = bs_u32 + (w << 11);
    const int s0 = lane, s1 = lane + 32;
    const int kk0 = s0 >> 2, sg0 = (s0 & 3) << 2;
    const int kk1 = s1 >> 2, sg1 = (s1 & 3) << 2;

    {
        int ka = min(kk0, K - 1), kb = min(kk1, K - 1);
        cpa16(bw + (s0 << 4), W + ka * 128 + wc0 + sg0);
        cpa16(bw + (s1 << 4), W + kb * 128 + wc0 + sg1);
        cpcommit();
    }

    for (int ch = 0; ch < NC; ch++) {
        if (ch + 1 < NC) {
            int kb2 = (ch + 1) << 4;
            int ka = min(kb2 + kk0, K - 1), kc = min(kb2 + kk1, K - 1);
            unsigned dst = bw + (((ch + 1) & 1) << 10);
            cpa16(dst + (s0 << 4), W + ka * 128 + wc0 + sg0);
            cpa16(dst + (s1 << 4), W + kc * 128 + wc0 + sg1);
            cpcommit();
            cpwait1();
        } else {
            cpwait0();
        }
        __syncwarp();
        const float* B = Bs + (w << 9) + ((ch & 1) << 8);
        const float* Ak = A + (ch << 4) * TM + r0;
        const float* Bk = B + ((lane >> 4) << 3);
#pragma unroll
        for (int kk = 0; kk < 16; kk++) {
            float4 a4 = *(const float4*)(Ak + (kk << 6));
            ulonglong2 b01 = *(const ulonglong2*)(Bk + (kk << 4));
            ulonglong2 b23 = *(const ulonglong2*)(Bk + (kk << 4) + 4);
            ull ar[4] = { pack2(a4.x, a4.x), pack2(a4.y, a4.y),
                          pack2(a4.z, a4.z), pack2(a4.w, a4.w) };
            ull bp[4] = { b01.x, b01.y, b23.x, b23.y };
#pragma unroll
            for (int r = 0; r < 4; r++)
#pragma unroll
                for (int cp = 0; cp < 4; cp++)
                    acc[r][cp] = fma2(ar[r], bp[cp], acc[r][cp]);
        }
        __syncwarp();
    }

#pragma unroll
    for (int cp = 0; cp < 4; cp++) {
        int c = c0 + (cp << 1);
        float lo, hi;
        float blo = bias[c], bhi = bias[c + 1];
#pragma unroll
        for (int r = 0; r < 4; r++) {
            unpack2(acc[r][cp], lo, hi);
            lo += blo; hi += bhi;
            Out[c * TM + r0 + r]       = lo > 0.f ? lo : 0.01f * lo;
            Out[(c + 1) * TM + r0 + r] = hi > 0.f ? hi : 0.01f * hi;
        }
    }
    __syncthreads();
}

// Row-spread output layer (small N): cooperative staging.
template<int NJ, bool SCATTER>
__device__ __forceinline__ void layer_rs(
    const float* A, int K, int NC,
    const float* __restrict__ W, int N, const float* __restrict__ bias,
    float* Out, float* Bs, int tid,
    const int* s_uv, float* uvmap, int m)
{
    const int w = tid >> 5, lane = tid & 31;
    const int r = (w << 3) + (lane >> 2);
    const int cg4 = lane & 3;

    float acc[NJ];
#pragma unroll
    for (int j = 0; j < NJ; j++) acc[j] = 0.f;

    float wpf[8];
#pragma unroll
    for (int t = 0; t < 8; t++) {
        int e = tid + (t << 8); int kk = e >> 7, j = e & 127;
        wpf[t] = (kk < K && j < N) ? W[kk * N + j] : 0.f;
    }

    for (int ch = 0; ch < NC; ch++) {
        float* B = Bs + ((ch & 1) << 11);
#pragma unroll
        for (int t = 0; t < 8; t++) B[tid + (t << 8)] = wpf[t];
        __syncthreads();
        if (ch + 1 < NC) {
            int kb = (ch + 1) << 4;
#pragma unroll
            for (int t = 0; t < 8; t++) {
                int e = tid + (t << 8); int kk = kb + (e >> 7), j = e & 127;
                wpf[t] = (kk < K && j < N) ? W[kk * N + j] : 0.f;
            }
        }
        const float* Ak = A + (ch << 4) * TM + r;
#pragma unroll
        for (int kk = 0; kk < 16; kk++) {
            float a = Ak[kk << 6];
            const float* Bk = B + (kk << 7) + cg4;
#pragma unroll
            for (int j = 0; j < NJ; j++)
                acc[j] += a * Bk[j << 2];
        }
        __syncthreads();
    }

    if (!SCATTER) {
#pragma unroll
        for (int j = 0; j < NJ; j++) {
            int c = cg4 + (j << 2);
            if (c < N) Out[c * TM + r] = acc[j] + bias[c];
        }
    } else {
        if (r < m) {
            int uv = s_uv[r];
#pragma unroll
            for (int j = 0; j < NJ; j++) {
                int c = cg4 + (j << 2);
                if (c < N) uvmap[c * UVE + uv] = acc[j] + bias[c];
            }
        }
    }
    __syncthreads();
}

__global__ __launch_bounds__(256, 2)
void mlp_k(const float* __restrict__ latent_z, const float* __restrict__ latent_f,
           const float* __restrict__ cano_xyz,
           const float* __restrict__ m1_w_in, const float* __restrict__ m1_b_in,
           const float* __restrict__ m1_w_hid, const float* __restrict__ m1_b_hid,
           const float* __restrict__ m1_w_out, const float* __restrict__ m1_b_out,
           const float* __restrict__ m2_w_in, const float* __restrict__ m2_b_in,
           const float* __restrict__ m2_w_hid, const float* __restrict__ m2_b_hid,
           const float* __restrict__ m2_w_out, const float* __restrict__ m2_b_out,
           const int* __restrict__ uv_idx,
           const int* __restrict__ order, const int* __restrict__ offsets,
           const int* __restrict__ tile_part, const int* __restrict__ tile_start,
           const int* __restrict__ ntiles,
           float* __restrict__ uvmap)
{
    extern __shared__ float sm[];
    float* Xs = sm;                        // [112][64]
    float* Hp = Xs + 112 * TM;             // [128][64]
    float* Hq = Hp + 128 * TM;             // [128][64]
    float* Bs = Hq + 128 * TM;             // 4096 floats
    int*   s_idx = (int*)(Bs + 4096);      // [64]
    int*   s_uv  = s_idx + TM;             // [64]

    if (blockIdx.x >= *ntiles) return;
    int p = tile_part[blockIdx.x];
    int start = tile_start[blockIdx.x];
    int m = min(TM, offsets[p + 1] - start);
    int tid = threadIdx.x;
    unsigned bs_u32 = smem_u32(Bs);

    if (tid < TM) {
        int rr = tid < m ? tid : (m - 1);
        int gid = order[start + rr];
        s_idx[tid] = gid;
        s_uv[tid] = uv_idx[gid];
    }
    __syncthreads();

    for (int e = tid; e < 112 * TM; e += 256) {
        int d = e >> 6, r = e & 63;
        float v = 0.f;
        if (d < 64)       v = latent_f[p * 64 + d];
        else if (d < 96)  v = latent_z[s_idx[r] * 32 + (d - 64)];
        else if (d < 99)  v = cano_xyz[s_idx[r] * 3 + (d - 96)];
        Xs[e] = v;
    }
    __syncthreads();

    layer2(Xs, 96, 6,  m1_w_in  + p * 96 * 128, m1_b_in  + p * 128, Hp, Bs, bs_u32, tid);
    layer2(Hp, 128, 8, m1_w_hid + (p * 2 + 0) * 16384, m1_b_hid + (p * 2 + 0) * 128, Hq, Bs, bs_u32, tid);
    layer2(Hq, 128, 8, m1_w_hid + (p * 2 + 1) * 16384, m1_b_hid + (p * 2 + 1) * 128, Hp, Bs, bs_u32, tid);
    layer_rs<3, false>(Hp, 128, 8, m1_w_out + p * 128 * 11, 11, m1_b_out + p * 11, Xs + 99 * TM, Bs, tid, 0, 0, m);
    layer2(Xs, 110, 7, m2_w_in  + p * 110 * 128, m2_b_in  + p * 128, Hp, Bs, bs_u32, tid);
    layer2(Hp, 128, 8, m2_w_hid + (p * 2 + 0) * 16384, m2_b_hid + (p * 2 + 0) * 128, Hq, Bs, bs_u32, tid);
    layer2(Hq, 128, 8, m2_w_hid + (p * 2 + 1) * 16384, m2_b_hid + (p * 2 + 1) * 128, Hp, Bs, bs_u32, tid);
    layer_rs<8, true>(Hp, 128, 8, m2_w_out + p * 128 * 32, 32, m2_b_out + p * 32, (float*)0, Bs, tid, s_uv, uvmap, m);
}

// ---------- CNN ----------
template<bool NORM, bool RELU, int TW>
__device__ __forceinline__ float conv_val(const float* __restrict__ in, int cin,
                                          int x0, int y0, int e, float mn, float is) {
    int row = e / TW, col = e - row * TW;
    int iy = y0 + row - 1, ix = x0 + col - 1;
    float v = 0.f;
    if (iy >= 0 && iy < 256 && ix >= 0 && ix < 256) {
        v = in[cin * UVE + iy * 256 + ix];
        if (NORM) v = (v - mn) * is;
        if (RELU) v = fmaxf(v, 0.f);
    }
    return v;
}

// Split-cout conv: 512 blocks = 256 tiles x 2 co-halves (32 couts each). 3 CTA/SM.
// Thread: 2x2 px (pg=tid&63) x 8 co (cg=tid>>6 -> 4 copairs). f32x2 over cout pairs.
template<int CIN, bool RELU, bool NORM, bool STATS>
__global__ __launch_bounds__(256, 3)
void conv32_k(const float* __restrict__ in, const float* __restrict__ wtf,
              const float* __restrict__ bias,
              const float* __restrict__ ps_in, const float* __restrict__ pq_in,
              float* __restrict__ out,
              float* __restrict__ ps_out, float* __restrict__ pq_out)
{
    __shared__ __align__(16) ull   tD[2][324];
    __shared__ __align__(16) float wsf[2][288];
    __shared__ float s_mn[64], s_is[64];

    const int bx = blockIdx.x;
    const int tile = bx & 255, h = bx >> 8;
    const int x0 = (tile & 15) << 4, y0 = (tile >> 4) << 4;
    const int tid = threadIdx.x;
    const int pg = tid & 63, cg = tid >> 6;
    const int lx = (pg & 7) << 1, ly = (pg >> 3) << 1;
    const int cob = (h << 5) + (cg << 3);

    if (NORM) {
        const int w = tid >> 5, lane = tid & 31;
#pragma unroll
        for (int c8 = 0; c8 < 8; c8++) {
            int c = (w << 3) + c8;
            float s = 0.f, q = 0.f;
            for (int t = lane; t < 512; t += 32) {
                s += ps_in[c * 512 + t];
                q += pq_in[c * 512 + t];
            }
#pragma unroll
            for (int d = 16; d >= 1; d >>= 1) {
                s += __shfl_down_sync(0xffffffffu, s, d);
                q += __shfl_down_sync(0xffffffffu, q, d);
            }
            if (lane == 0) {
                float mu = s * (1.f / UVE);
                s_mn[c] = mu;
                s_is[c] = rsqrtf(q * (1.f / UVE) - mu * mu + 1e-5f);
            }
        }
        __syncthreads();
    }

    ull acc[4][4];   // [copair][q]
#pragma unroll
    for (int cp = 0; cp < 4; cp++)
#pragma unroll
        for (int q = 0; q < 4; q++) acc[cp][q] = 0ull;

    float tv0, tv1 = 0.f;
    float wv0, wv1 = 0.f;
    {
        float mn = NORM ? s_mn[0] : 0.f, is = NORM ? s_is[0] : 1.f;
        tv0 = conv_val<NORM, RELU, 18>(in, 0, x0, y0, tid, mn, is);
        if (tid < 68) tv1 = conv_val<NORM, RELU, 18>(in, 0, x0, y0, tid + 256, mn, is);
        {
            int k = tid >> 5, j = tid & 31;
            wv0 = wtf[k * 64 + (h << 5) + j];
            if (tid < 32) wv1 = wtf[8 * 64 + (h << 5) + tid];
        }
    }

    for (int cin = 0; cin < CIN; cin++) {
        const int b = cin & 1;
        tD[b][tid] = pack2(tv0, tv0);
        if (tid < 68) tD[b][tid + 256] = pack2(tv1, tv1);
        wsf[b][tid] = wv0;
        if (tid < 32) wsf[b][tid + 256] = wv1;
        __syncthreads();
        if (cin + 1 < CIN) {
            int c2 = cin + 1;
            float mn = NORM ? s_mn[c2] : 0.f, is = NORM ? s_is[c2] : 1.f;
            tv0 = conv_val<NORM, RELU, 18>(in, c2, x0, y0, tid, mn, is);
            if (tid < 68) tv1 = conv_val<NORM, RELU, 18>(in, c2, x0, y0, tid + 256, mn, is);
            const float* wp = wtf + c2 * 576 + (h << 5);
            int k = tid >> 5, j = tid & 31;
            wv0 = wp[k * 64 + j];
            if (tid < 32) wv1 = wp[8 * 64 + tid];
        }
        const ull* td = tD[b];
        const float* wk = wsf[b] + (cg << 3);
#pragma unroll
        for (int ky = 0; ky < 3; ky++) {
            ulonglong2 ra0 = *(const ulonglong2*)&td[(ly + ky) * 18 + lx];
            ulonglong2 ra1 = *(const ulonglong2*)&td[(ly + ky) * 18 + lx + 2];
            ulonglong2 rb0 = *(const ulonglong2*)&td[(ly + ky + 1) * 18 + lx];
            ulonglong2 rb1 = *(const ulonglong2*)&td[(ly + ky + 1) * 18 + lx + 2];
            ull pa[4] = { ra0.x, ra0.y, ra1.x, ra1.y };
            ull pb[4] = { rb0.x, rb0.y, rb1.x, rb1.y };
#pragma unroll
            for (int kx = 0; kx < 3; kx++) {
#pragma unroll
                for (int cp2 = 0; cp2 < 2; cp2++) {
                    ulonglong2 w2 = *(const ulonglong2*)&wk[(ky * 3 + kx) * 32 + (cp2 << 2)];
                    int ce = cp2 << 1;
                    acc[ce][0]     = fma2(pa[kx],     w2.x, acc[ce][0]);
                    acc[ce][1]     = fma2(pa[kx + 1], w2.x, acc[ce][1]);
                    acc[ce][2]     = fma2(pb[kx],     w2.x, acc[ce][2]);
                    acc[ce][3]     = fma2(pb[kx + 1], w2.x, acc[ce][3]);
                    acc[ce + 1][0] = fma2(pa[kx],     w2.y, acc[ce + 1][0]);
                    acc[ce + 1][1] = fma2(pa[kx + 1], w2.y, acc[ce + 1][1]);
                    acc[ce + 1][2] = fma2(pb[kx],     w2.y, acc[ce + 1][2]);
                    acc[ce + 1][3] = fma2(pb[kx + 1], w2.y, acc[ce + 1][3]);
                }
            }
        }
    }

    const int wpar = (tid >> 5) & 1;
#pragma unroll
    for (int cp = 0; cp < 4; cp++) {
        int cA = cob + (cp << 1), cB = cA + 1;
        float bA = bias[cA], bB = bias[cB];
        float vA[4], vB[4];
#pragma unroll
        for (int q = 0; q < 4; q++) {
            unpack2(acc[cp][q], vA[q], vB[q]);
            vA[q] += bA; vB[q] += bB;
        }
        float* opA = out + cA * UVE + (y0 + ly) * 256 + (x0 + lx);
        float* opB = out + cB * UVE + (y0 + ly) * 256 + (x0 + lx);
        *(float2*)opA         = make_float2(vA[0], vA[1]);
        *(float2*)(opA + 256) = make_float2(vA[2], vA[3]);
        *(float2*)opB         = make_float2(vB[0], vB[1]);
        *(float2*)(opB + 256) = make_float2(vB[2], vB[3]);
        if (STATS) {
            float sA = vA[0] + vA[1] + vA[2] + vA[3];
            float qA = vA[0] * vA[0] + vA[1] * vA[1] + vA[2] * vA[2] + vA[3] * vA[3];
            float sB = vB[0] + vB[1] + vB[2] + vB[3];
            float qB = vB[0] * vB[0] + vB[1] * vB[1] + vB[2] * vB[2] + vB[3] * vB[3];
#pragma unroll
            for (int d = 16; d >= 1; d >>= 1) {
                sA += __shfl_down_sync(0xffffffffu, sA, d);
                qA += __shfl_down_sync(0xffffffffu, qA, d);
                sB += __shfl_down_sync(0xffffffffu, sB, d);
                qB += __shfl_down_sync(0xffffffffu, qB, d);
            }
            if ((tid & 31) == 0) {
                ps_out[cA * 512 + (tile << 1) + wpar] = sA;
                pq_out[cA * 512 + (tile << 1) + wpar] = qA;
                ps_out[cB * 512 + (tile << 1) + wpar] = sB;
                pq_out[cB * 512 + (tile << 1) + wpar] = qB;
            }
        }
    }
}

// conv_out: 64 -> 3, normalized input (prologue stats), sigmoid.
__global__ __launch_bounds__(256, 2)
void convout_k(const float* __restrict__ in, const float2* __restrict__ wt,
               const float* __restrict__ bias,
               const float* __restrict__ ps_in, const float* __restrict__ pq_in,
               float* __restrict__ out)
{
    __shared__ __align__(16) float tA[2][612];
    __shared__ __align__(16) float tB[2][616];
    __shared__ __align__(16) float2 wds[1728];
    __shared__ float s_mn[64], s_is[64];

    const int bx = blockIdx.x;
    const int x0 = (bx & 7) << 5, y0 = (bx >> 3) << 4;
    const int tid = threadIdx.x;
    const int lx = (tid & 15) << 1, ly = tid >> 4;

    {
        const int w = tid >> 5, lane = tid & 31;
#pragma unroll
        for (int c8 = 0; c8 < 8; c8++) {
            int c = (w << 3) + c8;
            float s = 0.f, q = 0.f;
            for (int t = lane; t < 512; t += 32) {
                s += ps_in[c * 512 + t];
                q += pq_in[c * 512 + t];
            }
#pragma unroll
            for (int d = 16; d >= 1; d >>= 1) {
                s += __shfl_down_sync(0xffffffffu, s, d);
                q += __shfl_down_sync(0xffffffffu, q, d);
            }
            if (lane == 0) {
                float mu = s * (1.f / UVE);
                s_mn[c] = mu;
                s_is[c] = rsqrtf(q * (1.f / UVE) - mu * mu + 1e-5f);
            }
        }
    }
    for (int e = tid; e < 1728; e += 256) wds[e] = wt[e];
    __syncthreads();

    ull acc0 = 0ull, acc1 = 0ull, acc2 = 0ull;

    float tv0, tv1 = 0.f, tv2 = 0.f;
    {
        float mn = s_mn[0], is = s_is[0];
        tv0 = conv_val<true, false, 34>(in, 0, x0, y0, tid, mn, is);
        tv1 = conv_val<true, false, 34>(in, 0, x0, y0, tid + 256, mn, is);
        if (tid < 100) tv2 = conv_val<true, false, 34>(in, 0, x0, y0, tid + 512, mn, is);
    }

    for (int cin = 0; cin < 64; cin++) {
        const int b = cin & 1;
        tA[b][tid] = tv0; tB[b][tid + 1] = tv0;
        tA[b][tid + 256] = tv1; tB[b][tid + 257] = tv1;
        if (tid < 100) { tA[b][tid + 512] = tv2; tB[b][tid + 513] = tv2; }
        __syncthreads();
        if (cin + 1 < 64) {
            int c2 = cin + 1;
            float mn = s_mn[c2], is = s_is[c2];
            tv0 = conv_val<true, false, 34>(in, c2, x0, y0, tid, mn, is);
            tv1 = conv_val<true, false, 34>(in, c2, x0, y0, tid + 256, mn, is);
            if (tid < 100) tv2 = conv_val<true, false, 34>(in, c2, x0, y0, tid + 512, mn, is);
        }
        ull pp[3][3];
#pragma unroll
        for (int r = 0; r < 3; r++) {
            int base = (ly + r) * 34 + lx;
            pp[r][0] = *(const ull*)&tA[b][base];
            pp[r][1] = *(const ull*)&tB[b][base + 2];
            pp[r][2] = *(const ull*)&tA[b][base + 2];
        }
        const float2* wc = wds + cin * 27;
#pragma unroll
        for (int r = 0; r < 3; r++)
#pragma unroll
            for (int kx = 0; kx < 3; kx++) {
                acc0 = fma2(pp[r][kx], *(const ull*)&wc[r * 3 + kx],      acc0);
                acc1 = fma2(pp[r][kx], *(const ull*)&wc[9 + r * 3 + kx],  acc1);
                acc2 = fma2(pp[r][kx], *(const ull*)&wc[18 + r * 3 + kx], acc2);
            }
        __syncthreads();
    }

    int o = (y0 + ly) * 256 + x0 + lx;
    float lo, hi;
    unpack2(acc0, lo, hi);
    *(float2*)(out + o) = make_float2(1.f / (1.f + __expf(-(lo + bias[0]))),
                                      1.f / (1.f + __expf(-(hi + bias[0]))));
    unpack2(acc1, lo, hi);
    *(float2*)(out + UVE + o) = make_float2(1.f / (1.f + __expf(-(lo + bias[1]))),
                                            1.f / (1.f + __expf(-(hi + bias[1]))));
    unpack2(acc2, lo, hi);
    *(float2*)(out + 2 * UVE + o) = make_float2(1.f / (1.f + __expf(-(lo + bias[2]))),
                                                1.f / (1.f + __expf(-(hi + bias[2]))));
}

// ---------- launch ----------
extern "C" void kernel_launch(void* const* d_in, const int* in_sizes, int n_in,
                              void* d_out, int out_size)
{
    const float* latent_z  = (const float*)d_in[0];
    const float* latent_f  = (const float*)d_in[1];
    const float* cano_xyz  = (const float*)d_in[2];
    const float* m1_w_in   = (const float*)d_in[3];
    const float* m1_b_in   = (const float*)d_in[4];
    const float* m1_w_hid  = (const float*)d_in[5];
    const float* m1_b_hid  = (const float*)d_in[6];
    const float* m1_w_out  = (const float*)d_in[7];
    const float* m1_b_out  = (const float*)d_in[8];
    const float* m2_w_in   = (const float*)d_in[9];
    const float* m2_b_in   = (const float*)d_in[10];
    const float* m2_w_hid  = (const float*)d_in[11];
    const float* m2_b_hid  = (const float*)d_in[12];
    const float* m2_w_out  = (const float*)d_in[13];
    const float* m2_b_out  = (const float*)d_in[14];
    const float* conv_in_w = (const float*)d_in[15];
    const float* conv_in_b = (const float*)d_in[16];
    const float* conv_hid_w= (const float*)d_in[17];
    const float* conv_hid_b= (const float*)d_in[18];
    const float* conv_out_w= (const float*)d_in[19];
    const float* conv_out_b= (const float*)d_in[20];
    const int*   gs_part   = (const int*)d_in[21];
    const int*   uv_idx    = (const int*)d_in[22];
    float* outp = (float*)d_out;

    void *p_counts, *p_offsets, *p_cursor, *p_order, *p_uvmap, *p_bufA, *p_bufB;
    void *p_wtf, *p_wt, *p_psA, *p_pqA, *p_psB, *p_pqB;
    void *p_tp, *p_ts, *p_nt;
    cudaGetSymbolAddress(&p_counts, g_counts);
    cudaGetSymbolAddress(&p_offsets, g_offsets);
    cudaGetSymbolAddress(&p_cursor, g_cursor);
    cudaGetSymbolAddress(&p_order, g_order);
    cudaGetSymbolAddress(&p_uvmap, g_uvmap);
    cudaGetSymbolAddress(&p_bufA, g_bufA);
    cudaGetSymbolAddress(&p_bufB, g_bufB);
    cudaGetSymbolAddress(&p_wtf, g_wtf);
    cudaGetSymbolAddress(&p_wt, g_wt);
    cudaGetSymbolAddress(&p_psA, g_psumA);
    cudaGetSymbolAddress(&p_pqA, g_psumsqA);
    cudaGetSymbolAddress(&p_psB, g_psumB);
    cudaGetSymbolAddress(&p_pqB, g_psumsqB);
    cudaGetSymbolAddress(&p_tp, g_tile_part);
    cudaGetSymbolAddress(&p_ts, g_tile_start);
    cudaGetSymbolAddress(&p_nt, g_ntiles);

    // Order keeps mlp_k as the 6th launch (ncu -s 5 -c 1 profiles it).
    cudaMemsetAsync(p_uvmap, 0, 32 * UVE * sizeof(float), 0);
    cudaMemsetAsync(p_counts, 0, 8 * sizeof(int), 0);

    int gb = (GN + 255) / 256;
    count_k<<<gb, 256>>>(gs_part, (int*)p_counts);
    scan_k<<<1, 32>>>((const int*)p_counts, (int*)p_offsets, (int*)p_cursor,
                      (int*)p_tp, (int*)p_ts, (int*)p_nt);
    scatter_k<<<gb, 256>>>(gs_part, (int*)p_cursor, (int*)p_order);

    static bool attr_set = false;
    if (!attr_set) {
        cudaFuncSetAttribute(mlp_k, cudaFuncAttributeMaxDynamicSharedMemorySize, 111104);
        attr_set = true;
    }
    mlp_k<<<630, 256, 111104>>>(
        latent_z, latent_f, cano_xyz,
        m1_w_in, m1_b_in, m1_w_hid, m1_b_hid, m1_w_out, m1_b_out,
        m2_w_in, m2_b_in, m2_w_hid, m2_b_hid, m2_w_out, m2_b_out,
        uv_idx, (const int*)p_order, (const int*)p_offsets,
        (const int*)p_tp, (const int*)p_ts, (const int*)p_nt, (float*)p_uvmap);

    wprep_k<<<432, 256>>>(conv_in_w, conv_hid_w, conv_out_w, (float*)p_wtf, (float2*)p_wt);

    float* bufA = (float*)p_bufA;
    float* bufB = (float*)p_bufB;
    float* psA = (float*)p_psA; float* pqA = (float*)p_pqA;
    float* psB = (float*)p_psB; float* pqB = (float*)p_pqB;
    const float* wtf = (const float*)p_wtf;

    conv32_k<32, false, false, false><<<512, 256>>>((const float*)p_uvmap, wtf, conv_in_b, 0, 0, bufA, 0, 0);
    conv32_k<64, true, false, true><<<512, 256>>>(bufA, wtf + 18432, conv_hid_b, 0, 0, bufB, psA, pqA);
    conv32_k<64, true, true, true><<<512, 256>>>(bufB, wtf + 18432 + 36864, conv_hid_b + 64, psA, pqA, bufA, psB, pqB);
    conv32_k<64, true, true, true><<<512, 256>>>(bufA, wtf + 18432 + 2 * 36864, conv_hid_b + 128, psB, pqB, bufB, psA, pqA);
    convout_k<<<128, 256>>>(bufB, (const float2*)p_wt, conv_out_b, psA, pqA, outp);
}

// round 17
// speedup vs baseline: 1.0670x; 1.0670x over previous
#include <cuda_runtime.h>
#include <math.h>

typedef unsigned long long ull;

#define GN 40000
#define PN 5
#define UVE 65536
#define TM 64

__device__ __forceinline__ ull fma2(ull a, ull b, ull c) {
    ull d; asm("fma.rn.f32x2 %0, %1, %2, %3;" : "=l"(d) : "l"(a), "l"(b), "l"(c)); return d;
}
__device__ __forceinline__ ull pack2(float lo, float hi) {
    ull d; asm("mov.b64 %0, {%1, %2};" : "=l"(d) : "f"(lo), "f"(hi)); return d;
}
__device__ __forceinline__ void unpack2(ull v, float& lo, float& hi) {
    asm("mov.b64 {%0, %1}, %2;" : "=f"(lo), "=f"(hi) : "l"(v));
}
__device__ __forceinline__ unsigned smem_u32(const void* p) {
    unsigned a;
    asm("{ .reg .u64 t; cvta.to.shared.u64 t, %1; cvt.u32.u64 %0, t; }" : "=r"(a) : "l"(p));
    return a;
}
__device__ __forceinline__ void cpa16(unsigned dst, const float* src) {
    asm volatile("cp.async.cg.shared.global [%0], [%1], 16;" :: "r"(dst), "l"(src));
}
__device__ __forceinline__ void cpcommit() { asm volatile("cp.async.commit_group;"); }
__device__ __forceinline__ void cpwait1() { asm volatile("cp.async.wait_group 1;"); }
__device__ __forceinline__ void cpwait0() { asm volatile("cp.async.wait_group 0;"); }

// ---------- scratch ----------
__device__ int    g_counts[8];
__device__ int    g_offsets[8];
__device__ int    g_cursor[8];
__device__ int    g_tile_part[640];
__device__ int    g_tile_start[640];
__device__ int    g_ntiles;
__device__ int    g_order[GN];
__device__ float  g_uvmap[32 * UVE];
__device__ float  g_bufA[64 * UVE];
__device__ float  g_bufB[64 * UVE];
__device__ float  g_psumA[64 * 512];
__device__ float  g_psumsqA[64 * 512];
__device__ float  g_psumB[64 * 512];
__device__ float  g_psumsqB[64 * 512];
__device__ float  g_wtf[129024];  // k-major: in[cin32][k9][co64]@0 ; hid[l][cin64][k9][co64]@18432
__device__ float2 g_wt[1728];     // convout dup: [cin64][co3][9]

// ---------- bucketing ----------
__global__ void count_k(const int* __restrict__ part, int* counts) {
    int g = blockIdx.x * blockDim.x + threadIdx.x;
    if (g < GN) atomicAdd(&counts[part[g]], 1);
}
__global__ void scan_k(const int* __restrict__ counts, int* offsets, int* cursor,
                       int* tile_part, int* tile_start, int* ntiles) {
    if (threadIdx.x == 0) {
        int s = 0, nt = 0;
        for (int p = 0; p < PN; p++) {
            offsets[p] = s; cursor[p] = s;
            for (int st = s; st < s + counts[p]; st += TM) {
                tile_part[nt] = p; tile_start[nt] = st; nt++;
            }
            s += counts[p];
        }
        offsets[PN] = s;
        *ntiles = nt;
    }
}
__global__ void scatter_k(const int* __restrict__ part, int* cursor, int* __restrict__ order) {
    int g = blockIdx.x * blockDim.x + threadIdx.x;
    if (g < GN) { int pos = atomicAdd(&cursor[part[g]], 1); order[pos] = g; }
}

// ---------- conv weight transpose ----------
__global__ void wprep_k(const float* __restrict__ win, const float* __restrict__ whid,
                        const float* __restrict__ wout, float* __restrict__ wtf,
                        float2* __restrict__ wt) {
    int i = blockIdx.x * 256 + threadIdx.x;
    if (i < 18432) {
        int k = i % 9; int t = i / 9; int co = t % 64, cin = t / 64;
        wtf[cin * 576 + k * 64 + co] = win[(co * 32 + cin) * 9 + k];
    }
    if (i < 110592) {
        int k = i % 9; int t = i / 9; int co = t % 64;
        int t2 = t / 64; int cin = t2 % 64, l = t2 / 64;
        wtf[18432 + l * 36864 + cin * 576 + k * 64 + co] = whid[((l * 64 + co) * 64 + cin) * 9 + k];
    }
    if (i < 1728) {
        int k = i % 9; int t = i / 9; int co = t % 3, cin = t / 3;
        float v = wout[(co * 64 + cin) * 9 + k];
        wt[i] = make_float2(v, v);
    }
}

// ---------- fused MLP: col-pack compute + cp.async per-warp weight staging ----------
__device__ __forceinline__ void layer2(
    const float* A, int K, int NC,
    const float* __restrict__ W, const float* __restrict__ bias,
    float* Out, float* Bs, unsigned bs_u32, int tid)
{
    const int w = tid >> 5, lane = tid & 31;
    const int r0 = (lane & 15) << 2;
    const int c0 = (w << 4) + ((lane >> 4) << 3);
    const int wc0 = w << 4;

    ull acc[4][4];
#pragma unroll
    for (int r = 0; r < 4; r++)
#pragma unroll
        for (int cp = 0; cp < 4; cp++) acc[r][cp] = 0ull;

    const unsigned bw = bs_u32 + (w << 11);
    const int s0 = lane, s1 = lane + 32;
    const int kk0 = s0 >> 2, sg0 = (s0 & 3) << 2;
    const int kk1 = s1 >> 2, sg1 = (s1 & 3) << 2;

    {
        int ka = min(kk0, K - 1), kb = min(kk1, K - 1);
        cpa16(bw + (s0 << 4), W + ka * 128 + wc0 + sg0);
        cpa16(bw + (s1 << 4), W + kb * 128 + wc0 + sg1);
        cpcommit();
    }

    for (int ch = 0; ch < NC; ch++) {
        if (ch + 1 < NC) {
            int kb2 = (ch + 1) << 4;
            int ka = min(kb2 + kk0, K - 1), kc = min(kb2 + kk1, K - 1);
            unsigned dst = bw + (((ch + 1) & 1) << 10);
            cpa16(dst + (s0 << 4), W + ka * 128 + wc0 + sg0);
            cpa16(dst + (s1 << 4), W + kc * 128 + wc0 + sg1);
            cpcommit();
            cpwait1();
        } else {
            cpwait0();
        }
        __syncwarp();
        const float* B = Bs + (w << 9) + ((ch & 1) << 8);
        const float* Ak = A + (ch << 4) * TM + r0;
        const float* Bk = B + ((lane >> 4) << 3);
#pragma unroll
        for (int kk = 0; kk < 16; kk++) {
            float4 a4 = *(const float4*)(Ak + (kk << 6));
            ulonglong2 b01 = *(const ulonglong2*)(Bk + (kk << 4));
            ulonglong2 b23 = *(const ulonglong2*)(Bk + (kk << 4) + 4);
            ull ar[4] = { pack2(a4.x, a4.x), pack2(a4.y, a4.y),
                          pack2(a4.z, a4.z), pack2(a4.w, a4.w) };
            ull bp[4] = { b01.x, b01.y, b23.x, b23.y };
#pragma unroll
            for (int r = 0; r < 4; r++)
#pragma unroll
                for (int cp = 0; cp < 4; cp++)
                    acc[r][cp] = fma2(ar[r], bp[cp], acc[r][cp]);
        }
        __syncwarp();
    }

#pragma unroll
    for (int cp = 0; cp < 4; cp++) {
        int c = c0 + (cp << 1);
        float lo, hi;
        float blo = bias[c], bhi = bias[c + 1];
#pragma unroll
        for (int r = 0; r < 4; r++) {
            unpack2(acc[r][cp], lo, hi);
            lo += blo; hi += bhi;
            Out[c * TM + r0 + r]       = lo > 0.f ? lo : 0.01f * lo;
            Out[(c + 1) * TM + r0 + r] = hi > 0.f ? hi : 0.01f * hi;
        }
    }
    __syncthreads();
}

// Row-spread output layer (small N): cooperative staging.
template<int NJ, bool SCATTER>
__device__ __forceinline__ void layer_rs(
    const float* A, int K, int NC,
    const float* __restrict__ W, int N, const float* __restrict__ bias,
    float* Out, float* Bs, int tid,
    const int* s_uv, float* uvmap, int m)
{
    const int w = tid >> 5, lane = tid & 31;
    const int r = (w << 3) + (lane >> 2);
    const int cg4 = lane & 3;

    float acc[NJ];
#pragma unroll
    for (int j = 0; j < NJ; j++) acc[j] = 0.f;

    float wpf[8];
#pragma unroll
    for (int t = 0; t < 8; t++) {
        int e = tid + (t << 8); int kk = e >> 7, j = e & 127;
        wpf[t] = (kk < K && j < N) ? W[kk * N + j] : 0.f;
    }

    for (int ch = 0; ch < NC; ch++) {
        float* B = Bs + ((ch & 1) << 11);
#pragma unroll
        for (int t = 0; t < 8; t++) B[tid + (t << 8)] = wpf[t];
        __syncthreads();
        if (ch + 1 < NC) {
            int kb = (ch + 1) << 4;
#pragma unroll
            for (int t = 0; t < 8; t++) {
                int e = tid + (t << 8); int kk = kb + (e >> 7), j = e & 127;
                wpf[t] = (kk < K && j < N) ? W[kk * N + j] : 0.f;
            }
        }
        const float* Ak = A + (ch << 4) * TM + r;
#pragma unroll
        for (int kk = 0; kk < 16; kk++) {
            float a = Ak[kk << 6];
            const float* Bk = B + (kk << 7) + cg4;
#pragma unroll
            for (int j = 0; j < NJ; j++)
                acc[j] += a * Bk[j << 2];
        }
        __syncthreads();
    }

    if (!SCATTER) {
#pragma unroll
        for (int j = 0; j < NJ; j++) {
            int c = cg4 + (j << 2);
            if (c < N) Out[c * TM + r] = acc[j] + bias[c];
        }
    } else {
        if (r < m) {
            int uv = s_uv[r];
#pragma unroll
            for (int j = 0; j < NJ; j++) {
                int c = cg4 + (j << 2);
                if (c < N) uvmap[c * UVE + uv] = acc[j] + bias[c];
            }
        }
    }
    __syncthreads();
}

__global__ __launch_bounds__(256, 2)
void mlp_k(const float* __restrict__ latent_z, const float* __restrict__ latent_f,
           const float* __restrict__ cano_xyz,
           const float* __restrict__ m1_w_in, const float* __restrict__ m1_b_in,
           const float* __restrict__ m1_w_hid, const float* __restrict__ m1_b_hid,
           const float* __restrict__ m1_w_out, const float* __restrict__ m1_b_out,
           const float* __restrict__ m2_w_in, const float* __restrict__ m2_b_in,
           const float* __restrict__ m2_w_hid, const float* __restrict__ m2_b_hid,
           const float* __restrict__ m2_w_out, const float* __restrict__ m2_b_out,
           const int* __restrict__ uv_idx,
           const int* __restrict__ order, const int* __restrict__ offsets,
           const int* __restrict__ tile_part, const int* __restrict__ tile_start,
           const int* __restrict__ ntiles,
           float* __restrict__ uvmap)
{
    extern __shared__ float sm[];
    float* Xs = sm;                        // [112][64]
    float* Hp = Xs + 112 * TM;             // [128][64]
    float* Hq = Hp + 128 * TM;             // [128][64]
    float* Bs = Hq + 128 * TM;             // 4096 floats
    int*   s_idx = (int*)(Bs + 4096);      // [64]
    int*   s_uv  = s_idx + TM;             // [64]

    if (blockIdx.x >= *ntiles) return;
    int p = tile_part[blockIdx.x];
    int start = tile_start[blockIdx.x];
    int m = min(TM, offsets[p + 1] - start);
    int tid = threadIdx.x;
    unsigned bs_u32 = smem_u32(Bs);

    if (tid < TM) {
        int rr = tid < m ? tid : (m - 1);
        int gid = order[start + rr];
        s_idx[tid] = gid;
        s_uv[tid] = uv_idx[gid];
    }
    __syncthreads();

    for (int e = tid; e < 112 * TM; e += 256) {
        int d = e >> 6, r = e & 63;
        float v = 0.f;
        if (d < 64)       v = latent_f[p * 64 + d];
        else if (d < 96)  v = latent_z[s_idx[r] * 32 + (d - 64)];
        else if (d < 99)  v = cano_xyz[s_idx[r] * 3 + (d - 96)];
        Xs[e] = v;
    }
    __syncthreads();

    layer2(Xs, 96, 6,  m1_w_in  + p * 96 * 128, m1_b_in  + p * 128, Hp, Bs, bs_u32, tid);
    layer2(Hp, 128, 8, m1_w_hid + (p * 2 + 0) * 16384, m1_b_hid + (p * 2 + 0) * 128, Hq, Bs, bs_u32, tid);
    layer2(Hq, 128, 8, m1_w_hid + (p * 2 + 1) * 16384, m1_b_hid + (p * 2 + 1) * 128, Hp, Bs, bs_u32, tid);
    layer_rs<3, false>(Hp, 128, 8, m1_w_out + p * 128 * 11, 11, m1_b_out + p * 11, Xs + 99 * TM, Bs, tid, 0, 0, m);
    layer2(Xs, 110, 7, m2_w_in  + p * 110 * 128, m2_b_in  + p * 128, Hp, Bs, bs_u32, tid);
    layer2(Hp, 128, 8, m2_w_hid + (p * 2 + 0) * 16384, m2_b_hid + (p * 2 + 0) * 128, Hq, Bs, bs_u32, tid);
    layer2(Hq, 128, 8, m2_w_hid + (p * 2 + 1) * 16384, m2_b_hid + (p * 2 + 1) * 128, Hp, Bs, bs_u32, tid);
    layer_rs<8, true>(Hp, 128, 8, m2_w_out + p * 128 * 32, 32, m2_b_out + p * 32, (float*)0, Bs, tid, s_uv, uvmap, m);
}

// ---------- CNN ----------
template<bool NORM, bool RELU, int TW>
__device__ __forceinline__ float conv_val(const float* __restrict__ in, int cin,
                                          int x0, int y0, int e, float mn, float is) {
    int row = e / TW, col = e - row * TW;
    int iy = y0 + row - 1, ix = x0 + col - 1;
    float v = 0.f;
    if (iy >= 0 && iy < 256 && ix >= 0 && ix < 256) {
        v = in[cin * UVE + iy * 256 + ix];
        if (NORM) v = (v - mn) * is;
        if (RELU) v = fmaxf(v, 0.f);
    }
    return v;
}

// 16x16 px x 64 co per block. Thread: 2x2 px x 16 co. f32x2 packed over COUT pairs.
template<int CIN, bool RELU, bool NORM, bool STATS>
__global__ __launch_bounds__(256, 2)
void conv64_k(const float* __restrict__ in, const float* __restrict__ wtf,
              const float* __restrict__ bias,
              const float* __restrict__ ps_in, const float* __restrict__ pq_in,
              float* __restrict__ out,
              float* __restrict__ ps_out, float* __restrict__ pq_out)
{
    __shared__ __align__(16) ull   tD[2][324];
    __shared__ __align__(16) float wsf[2][576];
    __shared__ float s_mn[64], s_is[64];

    const int bx = blockIdx.x;
    const int x0 = (bx & 15) << 4, y0 = (bx >> 4) << 4;
    const int tid = threadIdx.x;
    const int pg = tid & 63, cg = tid >> 6;
    const int lx = (pg & 7) << 1, ly = (pg >> 3) << 1;

    if (NORM) {
        const int w = tid >> 5, lane = tid & 31;
#pragma unroll
        for (int c8 = 0; c8 < 8; c8++) {
            int c = (w << 3) + c8;
            float s = 0.f, q = 0.f;
            for (int t = lane; t < 512; t += 32) {
                s += ps_in[c * 512 + t];
                q += pq_in[c * 512 + t];
            }
#pragma unroll
            for (int d = 16; d >= 1; d >>= 1) {
                s += __shfl_down_sync(0xffffffffu, s, d);
                q += __shfl_down_sync(0xffffffffu, q, d);
            }
            if (lane == 0) {
                float mu = s * (1.f / UVE);
                s_mn[c] = mu;
                s_is[c] = rsqrtf(q * (1.f / UVE) - mu * mu + 1e-5f);
            }
        }
        __syncthreads();
    }

    ull acc[8][4];
#pragma unroll
    for (int cp = 0; cp < 8; cp++)
#pragma unroll
        for (int q = 0; q < 4; q++) acc[cp][q] = 0ull;

    float tv0, tv1 = 0.f;
    float wv0, wv1, wv2 = 0.f;
    {
        float mn = NORM ? s_mn[0] : 0.f, is = NORM ? s_is[0] : 1.f;
        tv0 = conv_val<NORM, RELU, 18>(in, 0, x0, y0, tid, mn, is);
        if (tid < 68) tv1 = conv_val<NORM, RELU, 18>(in, 0, x0, y0, tid + 256, mn, is);
        wv0 = wtf[tid]; wv1 = wtf[tid + 256];
        if (tid < 64) wv2 = wtf[tid + 512];
    }

    for (int cin = 0; cin < CIN; cin++) {
        const int b = cin & 1;
        tD[b][tid] = pack2(tv0, tv0);
        if (tid < 68) tD[b][tid + 256] = pack2(tv1, tv1);
        wsf[b][tid] = wv0; wsf[b][tid + 256] = wv1;
        if (tid < 64) wsf[b][tid + 512] = wv2;
        __syncthreads();
        if (cin + 1 < CIN) {
            int c2 = cin + 1;
            float mn = NORM ? s_mn[c2] : 0.f, is = NORM ? s_is[c2] : 1.f;
            tv0 = conv_val<NORM, RELU, 18>(in, c2, x0, y0, tid, mn, is);
            if (tid < 68) tv1 = conv_val<NORM, RELU, 18>(in, c2, x0, y0, tid + 256, mn, is);
            const float* wp = wtf + c2 * 576;
            wv0 = wp[tid]; wv1 = wp[tid + 256];
            if (tid < 64) wv2 = wp[tid + 512];
        }
        const ull* td = tD[b];
        const float* wk = wsf[b] + (cg << 4);
#pragma unroll
        for (int ky = 0; ky < 3; ky++) {
            ulonglong2 ra0 = *(const ulonglong2*)&td[(ly + ky) * 18 + lx];
            ulonglong2 ra1 = *(const ulonglong2*)&td[(ly + ky) * 18 + lx + 2];
            ulonglong2 rb0 = *(const ulonglong2*)&td[(ly + ky + 1) * 18 + lx];
            ulonglong2 rb1 = *(const ulonglong2*)&td[(ly + ky + 1) * 18 + lx + 2];
            ull pa[4] = { ra0.x, ra0.y, ra1.x, ra1.y };
            ull pb[4] = { rb0.x, rb0.y, rb1.x, rb1.y };
#pragma unroll
            for (int kx = 0; kx < 3; kx++) {
#pragma unroll
                for (int cp2 = 0; cp2 < 4; cp2++) {
                    ulonglong2 w2 = *(const ulonglong2*)&wk[(ky * 3 + kx) * 64 + (cp2 << 2)];
                    int ce = cp2 << 1;
                    acc[ce][0]     = fma2(pa[kx],     w2.x, acc[ce][0]);
                    acc[ce][1]     = fma2(pa[kx + 1], w2.x, acc[ce][1]);
                    acc[ce][2]     = fma2(pb[kx],     w2.x, acc[ce][2]);
                    acc[ce][3]     = fma2(pb[kx + 1], w2.x, acc[ce][3]);
                    acc[ce + 1][0] = fma2(pa[kx],     w2.y, acc[ce + 1][0]);
                    acc[ce + 1][1] = fma2(pa[kx + 1], w2.y, acc[ce + 1][1]);
                    acc[ce + 1][2] = fma2(pb[kx],     w2.y, acc[ce + 1][2]);
                    acc[ce + 1][3] = fma2(pb[kx + 1], w2.y, acc[ce + 1][3]);
                }
            }
        }
    }

    const int wpar = (tid >> 5) & 1;
#pragma unroll
    for (int cp = 0; cp < 8; cp++) {
        int cA = (cg << 4) + (cp << 1), cB = cA + 1;
        float bA = bias[cA], bB = bias[cB];
        float vA[4], vB[4];
#pragma unroll
        for (int q = 0; q < 4; q++) {
            unpack2(acc[cp][q], vA[q], vB[q]);
            vA[q] += bA; vB[q] += bB;
        }
        float* opA = out + cA * UVE + (y0 + ly) * 256 + (x0 + lx);
        float* opB = out + cB * UVE + (y0 + ly) * 256 + (x0 + lx);
        *(float2*)opA         = make_float2(vA[0], vA[1]);
        *(float2*)(opA + 256) = make_float2(vA[2], vA[3]);
        *(float2*)opB         = make_float2(vB[0], vB[1]);
        *(float2*)(opB + 256) = make_float2(vB[2], vB[3]);
        if (STATS) {
            float sA = vA[0] + vA[1] + vA[2] + vA[3];
            float qA = vA[0] * vA[0] + vA[1] * vA[1] + vA[2] * vA[2] + vA[3] * vA[3];
            float sB = vB[0] + vB[1] + vB[2] + vB[3];
            float qB = vB[0] * vB[0] + vB[1] * vB[1] + vB[2] * vB[2] + vB[3] * vB[3];
#pragma unroll
            for (int d = 16; d >= 1; d >>= 1) {
                sA += __shfl_down_sync(0xffffffffu, sA, d);
                qA += __shfl_down_sync(0xffffffffu, qA, d);
                sB += __shfl_down_sync(0xffffffffu, sB, d);
                qB += __shfl_down_sync(0xffffffffu, qB, d);
            }
            if ((tid & 31) == 0) {
                ps_out[cA * 512 + (bx << 1) + wpar] = sA;
                pq_out[cA * 512 + (bx << 1) + wpar] = qA;
                ps_out[cB * 512 + (bx << 1) + wpar] = sB;
                pq_out[cB * 512 + (bx << 1) + wpar] = qB;
            }
        }
    }
}

// conv_out: 64 -> 3, normalized input (prologue stats), sigmoid.
__global__ __launch_bounds__(256, 2)
void convout_k(const float* __restrict__ in, const float2* __restrict__ wt,
               const float* __restrict__ bias,
               const float* __restrict__ ps_in, const float* __restrict__ pq_in,
               float* __restrict__ out)
{
    __shared__ __align__(16) float tA[2][612];
    __shared__ __align__(16) float tB[2][616];
    __shared__ __align__(16) float2 wds[1728];
    __shared__ float s_mn[64], s_is[64];

    const int bx = blockIdx.x;
    const int x0 = (bx & 7) << 5, y0 = (bx >> 3) << 4;
    const int tid = threadIdx.x;
    const int lx = (tid & 15) << 1, ly = tid >> 4;

    {
        const int w = tid >> 5, lane = tid & 31;
#pragma unroll
        for (int c8 = 0; c8 < 8; c8++) {
            int c = (w << 3) + c8;
            float s = 0.f, q = 0.f;
            for (int t = lane; t < 512; t += 32) {
                s += ps_in[c * 512 + t];
                q += pq_in[c * 512 + t];
            }
#pragma unroll
            for (int d = 16; d >= 1; d >>= 1) {
                s += __shfl_down_sync(0xffffffffu, s, d);
                q += __shfl_down_sync(0xffffffffu, q, d);
            }
            if (lane == 0) {
                float mu = s * (1.f / UVE);
                s_mn[c] = mu;
                s_is[c] = rsqrtf(q * (1.f / UVE) - mu * mu + 1e-5f);
            }
        }
    }
    for (int e = tid; e < 1728; e += 256) wds[e] = wt[e];
    __syncthreads();

    ull acc0 = 0ull, acc1 = 0ull, acc2 = 0ull;

    float tv0, tv1 = 0.f, tv2 = 0.f;
    {
        float mn = s_mn[0], is = s_is[0];
        tv0 = conv_val<true, false, 34>(in, 0, x0, y0, tid, mn, is);
        tv1 = conv_val<true, false, 34>(in, 0, x0, y0, tid + 256, mn, is);
        if (tid < 100) tv2 = conv_val<true, false, 34>(in, 0, x0, y0, tid + 512, mn, is);
    }

    for (int cin = 0; cin < 64; cin++) {
        const int b = cin & 1;
        tA[b][tid] = tv0; tB[b][tid + 1] = tv0;
        tA[b][tid + 256] = tv1; tB[b][tid + 257] = tv1;
        if (tid < 100) { tA[b][tid + 512] = tv2; tB[b][tid + 513] = tv2; }
        __syncthreads();
        if (cin + 1 < 64) {
            int c2 = cin + 1;
            float mn = s_mn[c2], is = s_is[c2];
            tv0 = conv_val<true, false, 34>(in, c2, x0, y0, tid, mn, is);
            tv1 = conv_val<true, false, 34>(in, c2, x0, y0, tid + 256, mn, is);
            if (tid < 100) tv2 = conv_val<true, false, 34>(in, c2, x0, y0, tid + 512, mn, is);
        }
        ull pp[3][3];
#pragma unroll
        for (int r = 0; r < 3; r++) {
            int base = (ly + r) * 34 + lx;
            pp[r][0] = *(const ull*)&tA[b][base];
            pp[r][1] = *(const ull*)&tB[b][base + 2];
            pp[r][2] = *(const ull*)&tA[b][base + 2];
        }
        const float2* wc = wds + cin * 27;
#pragma unroll
        for (int r = 0; r < 3; r++)
#pragma unroll
            for (int kx = 0; kx < 3; kx++) {
                acc0 = fma2(pp[r][kx], *(const ull*)&wc[r * 3 + kx],      acc0);
                acc1 = fma2(pp[r][kx], *(const ull*)&wc[9 + r * 3 + kx],  acc1);
                acc2 = fma2(pp[r][kx], *(const ull*)&wc[18 + r * 3 + kx], acc2);
            }
        __syncthreads();
    }

    int o = (y0 + ly) * 256 + x0 + lx;
    float lo, hi;
    unpack2(acc0, lo, hi);
    *(float2*)(out + o) = make_float2(1.f / (1.f + __expf(-(lo + bias[0]))),
                                      1.f / (1.f + __expf(-(hi + bias[0]))));
    unpack2(acc1, lo, hi);
    *(float2*)(out + UVE + o) = make_float2(1.f / (1.f + __expf(-(lo + bias[1]))),
                                            1.f / (1.f + __expf(-(hi + bias[1]))));
    unpack2(acc2, lo, hi);
    *(float2*)(out + 2 * UVE + o) = make_float2(1.f / (1.f + __expf(-(lo + bias[2]))),
                                                1.f / (1.f + __expf(-(hi + bias[2]))));
}

// ---------- launch ----------
extern "C" void kernel_launch(void* const* d_in, const int* in_sizes, int n_in,
                              void* d_out, int out_size)
{
    const float* latent_z  = (const float*)d_in[0];
    const float* latent_f  = (const float*)d_in[1];
    const float* cano_xyz  = (const float*)d_in[2];
    const float* m1_w_in   = (const float*)d_in[3];
    const float* m1_b_in   = (const float*)d_in[4];
    const float* m1_w_hid  = (const float*)d_in[5];
    const float* m1_b_hid  = (const float*)d_in[6];
    const float* m1_w_out  = (const float*)d_in[7];
    const float* m1_b_out  = (const float*)d_in[8];
    const float* m2_w_in   = (const float*)d_in[9];
    const float* m2_b_in   = (const float*)d_in[10];
    const float* m2_w_hid  = (const float*)d_in[11];
    const float* m2_b_hid  = (const float*)d_in[12];
    const float* m2_w_out  = (const float*)d_in[13];
    const float* m2_b_out  = (const float*)d_in[14];
    const float* conv_in_w = (const float*)d_in[15];
    const float* conv_in_b = (const float*)d_in[16];
    const float* conv_hid_w= (const float*)d_in[17];
    const float* conv_hid_b= (const float*)d_in[18];
    const float* conv_out_w= (const float*)d_in[19];
    const float* conv_out_b= (const float*)d_in[20];
    const int*   gs_part   = (const int*)d_in[21];
    const int*   uv_idx    = (const int*)d_in[22];
    float* outp = (float*)d_out;

    void *p_counts, *p_offsets, *p_cursor, *p_order, *p_uvmap, *p_bufA, *p_bufB;
    void *p_wtf, *p_wt, *p_psA, *p_pqA, *p_psB, *p_pqB;
    void *p_tp, *p_ts, *p_nt;
    cudaGetSymbolAddress(&p_counts, g_counts);
    cudaGetSymbolAddress(&p_offsets, g_offsets);
    cudaGetSymbolAddress(&p_cursor, g_cursor);
    cudaGetSymbolAddress(&p_order, g_order);
    cudaGetSymbolAddress(&p_uvmap, g_uvmap);
    cudaGetSymbolAddress(&p_bufA, g_bufA);
    cudaGetSymbolAddress(&p_bufB, g_bufB);
    cudaGetSymbolAddress(&p_wtf, g_wtf);
    cudaGetSymbolAddress(&p_wt, g_wt);
    cudaGetSymbolAddress(&p_psA, g_psumA);
    cudaGetSymbolAddress(&p_pqA, g_psumsqA);
    cudaGetSymbolAddress(&p_psB, g_psumB);
    cudaGetSymbolAddress(&p_pqB, g_psumsqB);
    cudaGetSymbolAddress(&p_tp, g_tile_part);
    cudaGetSymbolAddress(&p_ts, g_tile_start);
    cudaGetSymbolAddress(&p_nt, g_ntiles);

    // Order keeps mlp_k as the 6th launch (ncu -s 5 -c 1 profiles it).
    cudaMemsetAsync(p_uvmap, 0, 32 * UVE * sizeof(float), 0);
    cudaMemsetAsync(p_counts, 0, 8 * sizeof(int), 0);

    int gb = (GN + 255) / 256;
    count_k<<<gb, 256>>>(gs_part, (int*)p_counts);
    scan_k<<<1, 32>>>((const int*)p_counts, (int*)p_offsets, (int*)p_cursor,
                      (int*)p_tp, (int*)p_ts, (int*)p_nt);
    scatter_k<<<gb, 256>>>(gs_part, (int*)p_cursor, (int*)p_order);

    static bool attr_set = false;
    if (!attr_set) {
        cudaFuncSetAttribute(mlp_k, cudaFuncAttributeMaxDynamicSharedMemorySize, 111104);
        attr_set = true;
    }
    mlp_k<<<630, 256, 111104>>>(
        latent_z, latent_f, cano_xyz,
        m1_w_in, m1_b_in, m1_w_hid, m1_b_hid, m1_w_out, m1_b_out,
        m2_w_in, m2_b_in, m2_w_hid, m2_b_hid, m2_w_out, m2_b_out,
        uv_idx, (const int*)p_order, (const int*)p_offsets,
        (const int*)p_tp, (const int*)p_ts, (const int*)p_nt, (float*)p_uvmap);

    wprep_k<<<432, 256>>>(conv_in_w, conv_hid_w, conv_out_w, (float*)p_wtf, (float2*)p_wt);

    float* bufA = (float*)p_bufA;
    float* bufB = (float*)p_bufB;
    float* psA = (float*)p_psA; float* pqA = (float*)p_pqA;
    float* psB = (float*)p_psB; float* pqB = (float*)p_pqB;
    const float* wtf = (const float*)p_wtf;

    conv64_k<32, false, false, false><<<256, 256>>>((const float*)p_uvmap, wtf, conv_in_b, 0, 0, bufA, 0, 0);
    conv64_k<64, true, false, true><<<256, 256>>>(bufA, wtf + 18432, conv_hid_b, 0, 0, bufB, psA, pqA);
    conv64_k<64, true, true, true><<<256, 256>>>(bufB, wtf + 18432 + 36864, conv_hid_b + 64, psA, pqA, bufA, psB, pqB);
    conv64_k<64, true, true, true><<<256, 256>>>(bufA, wtf + 18432 + 2 * 36864, conv_hid_b + 128, psB, pqB, bufB, psA, pqA);
    convout_k<<<128, 256>>>(bufB, (const float2*)p_wt, conv_out_b, psA, pqA, outp);
}